// round 17
// baseline (speedup 1.0000x reference)
#include <cuda_runtime.h>
#include <cuda_fp16.h>
#include <cstdint>

// PatchEmbedding, fp16 tensor path, split-grid producer/consumer overlap:
//   1) round_wh: W -> fp16 Wh [768,704] (padded); zeroes per-panel flags.
//   2) gemm kernel, grid = 74 producers + 882 consumers:
//      - producer CTA (bid < 74): gathers whole panels (panel = bid, bid+74)
//        into g_Ah (fp16, padded), release-stores g_flag[panel] = 1.
//      - consumer CTA: polls its panel flag, then runs the proven cp.async
//        3-stage mma.m16n8k16.f16 GEMM: BM=256 x BN=128, 512 thr (4Mx4N),
//        warp tile 64x32, fragment double-buffering. D = A*W^T + bias.

namespace {

constexpr int C_   = 4;
constexpr int Himg = 420;
constexpr int Wimg = 312;
constexpr int PH   = 14;
constexpr int PW   = 12;
constexpr int GW   = 26;
constexpr int E    = 768;
constexpr int NV   = 390;
constexpr int K    = 672;
constexpr int Kp   = 704;            // padded K (multiple of 64)
constexpr int Kp4  = Kp / 4;         // 176 half4-groups per row
constexpr int K4   = K / 4;          // 168 valid groups
constexpr int M    = 96 * NV;        // 37440
constexpr int HW_  = Himg * Wimg;
constexpr int CHW  = C_ * HW_;

constexpr int BM = 256, BN = 128, BK = 64;   // BK in fp16 elements (128 B)
constexpr int NKT    = Kp / BK;              // 11
constexpr int NBLK   = E / BN;               // 6
constexpr int MBLK   = (M + BM - 1) / BM;    // 147 panels
constexpr int NPROD  = 74;                   // producer CTAs
constexpr int STAGES = 3;
constexpr int A_BYTES = BM * BK * 2;               // 32 KB
constexpr int STAGE_BYTES = (BM + BN) * BK * 2;    // 48 KB
constexpr int SM_TOTAL = STAGES * STAGE_BYTES;     // 144 KB

constexpr int NW4 = E * Kp4;         // W half4-groups

} // namespace

// scratch (module-scope device globals; allocation-free at launch time)
__device__ __align__(16) __half g_Ah[(size_t)M * Kp];   // ~52.7 MB
__device__ __align__(16) __half g_Wh[(size_t)E * Kp];   // ~1.1 MB
__device__ int g_flag[MBLK];                            // panel-ready flags

namespace {

__device__ __forceinline__ uint32_t smem_u32(const void* p) {
    uint32_t a;
    asm("{ .reg .u64 t; cvta.to.shared.u64 t, %1; cvt.u32.u64 %0, t; }"
        : "=r"(a) : "l"(p));
    return a;
}

__device__ __forceinline__ void cp16(uint32_t dst, const void* src) {
    asm volatile("cp.async.cg.shared.global [%0], [%1], 16;"
                 :: "r"(dst), "l"(src) : "memory");
}

__device__ __forceinline__ void ldsm_x4(uint32_t r[4], uint32_t addr) {
    asm volatile("ldmatrix.sync.aligned.m8n8.x4.shared.b16 {%0,%1,%2,%3}, [%4];"
                 : "=r"(r[0]), "=r"(r[1]), "=r"(r[2]), "=r"(r[3]) : "r"(addr));
}

__device__ __forceinline__ void mma_f16(float d[4], const uint32_t a[4],
                                        uint32_t b0, uint32_t b1) {
    asm volatile(
        "mma.sync.aligned.m16n8k16.row.col.f32.f16.f16.f32 "
        "{%0,%1,%2,%3}, {%4,%5,%6,%7}, {%8,%9}, {%0,%1,%2,%3};"
        : "+f"(d[0]), "+f"(d[1]), "+f"(d[2]), "+f"(d[3])
        : "r"(a[0]), "r"(a[1]), "r"(a[2]), "r"(a[3]), "r"(b0), "r"(b1));
}

__device__ __forceinline__ uint2 pack4(float4 v) {
    __half2 lo = __floats2half2_rn(v.x, v.y);
    __half2 hi = __floats2half2_rn(v.z, v.w);
    uint2 r;
    r.x = *reinterpret_cast<uint32_t*>(&lo);
    r.y = *reinterpret_cast<uint32_t*>(&hi);
    return r;
}

// ---- pre-pass: W -> fp16 padded; zero panel flags ----
__global__ void round_wh(const float* __restrict__ Wm) {
    int idx = blockIdx.x * blockDim.x + threadIdx.x;   // half4-group id
    if (idx < MBLK) g_flag[idx] = 0;
    if (idx >= NW4) return;
    int e = idx / Kp4;
    int t = idx - e * Kp4;
    uint2 val = make_uint2(0, 0);
    if (t < K4)
        val = pack4(*reinterpret_cast<const float4*>(Wm + (size_t)e * K + t * 4));
    *reinterpret_cast<uint2*>(g_Wh + (size_t)e * Kp + t * 4) = val;
}

// ---- split-grid kernel: producers gather panels; consumers run GEMM ----
__global__ __launch_bounds__(512)
void patch_embed_gemm(const float* __restrict__ x,
                      const float* __restrict__ bias,
                      const int*   __restrict__ valid,
                      float*       __restrict__ out)
{
    extern __shared__ char smem[];
    const uint32_t sb = smem_u32(smem);

    const int tid  = threadIdx.x;
    const int lane = tid & 31;
    const int wid  = tid >> 5;
    const int bid  = blockIdx.x;

    // ================= producer CTAs =================
    if (bid < NPROD) {
        for (int panel = bid; panel < MBLK; panel += NPROD) {
            const int m0p = panel * BM;
            for (int rr = wid; rr < BM; rr += 16) {     // warp per row
                int m = m0p + rr;
                if (m >= M) break;
                int n  = m / NV;
                int v  = m - n * NV;
                int p  = __ldg(valid + v);
                int gi = p / GW;
                int gj = p - gi * GW;
                const float* xrow = x + n * CHW + gi * (PH * Wimg) + gj * PW;
                __half* dst = g_Ah + (size_t)m * Kp;
                #pragma unroll
                for (int g = lane; g < Kp4; g += 32) {
                    uint2 w = make_uint2(0, 0);
                    if (g < K4) {
                        int c  = g / 42;     // 42 groups/channel (14 rows x 3)
                        int r3 = g - c * 42;
                        int r  = r3 / 3;
                        int q4 = r3 - r * 3;
                        w = pack4(*reinterpret_cast<const float4*>(
                            xrow + c * HW_ + r * Wimg + q4 * 4));
                    }
                    *reinterpret_cast<uint2*>(dst + g * 4) = w;
                }
            }
            __syncthreads();
            __threadfence();          // all threads: release panel writes
            __syncthreads();
            if (tid == 0) atomicExch(&g_flag[panel], 1);
        }
        return;
    }

    // ================= consumer CTAs =================
    const int cid   = bid - NPROD;
    const int nb    = cid % NBLK;        // n-block (innermost -> L2 reuse)
    const int panel = cid / NBLK;
    const int n0    = nb * BN;
    const int m0    = panel * BM;

    if (tid == 0) {
        while (atomicAdd(&g_flag[panel], 0) == 0) __nanosleep(128);
        __threadfence();                 // acquire producer writes
    }
    __syncthreads();

    // ---- proven 3-stage cp.async GEMM ----
    const int      ar_t = tid >> 1;
    const int      acb  = (tid & 1) * 64;
    const uint32_t xma  = (ar_t << 4) & 0x70;
    const int      arow = (m0 + ar_t < M) ? (m0 + ar_t) : (M - 1);
    const __half*  asrc = g_Ah + (size_t)arow * Kp + (tid & 1) * 32;
    const int      br_t = tid >> 2;
    const int      bcb  = (tid & 3) * 32;
    const uint32_t xmb  = (br_t << 4) & 0x70;
    const __half*  bsrc = g_Wh + (size_t)(n0 + br_t) * Kp + (tid & 3) * 16;

    auto issue = [&](int kt) {
        const uint32_t st = sb + (kt % STAGES) * STAGE_BYTES;
        const __half* as = asrc + kt * BK;
        const __half* bs = bsrc + kt * BK;
        const uint32_t abase = st + ar_t * 128;
        #pragma unroll
        for (int j = 0; j < 4; ++j)
            cp16(abase + ((uint32_t)(acb + j * 16) ^ xma), as + j * 8);
        const uint32_t bbase = st + A_BYTES + br_t * 128;
        #pragma unroll
        for (int j = 0; j < 2; ++j)
            cp16(bbase + ((uint32_t)(bcb + j * 16) ^ xmb), bs + j * 8);
    };

    const int wm = (wid & 3) * 64;
    const int wn = (wid >> 2) * 32;
    const int row_l = lane & 15;
    const int q_l   = lane >> 4;
    const uint32_t mask_a = (uint32_t)(((wm + row_l) << 4) & 0x70);
    const uint32_t mask_b = (uint32_t)(((wn + row_l) << 4) & 0x70);
    const uint32_t abase_t = (uint32_t)((wm + row_l) * 128);
    const uint32_t bbase_t = (uint32_t)((wn + row_l) * 128);

    float d[4][4][4];
    #pragma unroll
    for (int i = 0; i < 4; ++i)
        #pragma unroll
        for (int j = 0; j < 4; ++j)
            #pragma unroll
            for (int r = 0; r < 4; ++r)
                d[i][j][r] = 0.0f;

    issue(0);
    asm volatile("cp.async.commit_group;" ::: "memory");
    issue(1);
    asm volatile("cp.async.commit_group;" ::: "memory");

    uint32_t a[2][4][4];
    uint32_t b[2][2][4];

    for (int kt = 0; kt < NKT; ++kt) {
        asm volatile("cp.async.wait_group 1;" ::: "memory");
        __syncthreads();

        if (kt + 2 < NKT) issue(kt + 2);
        asm volatile("cp.async.commit_group;" ::: "memory");

        const uint32_t astg = sb + (kt % STAGES) * STAGE_BYTES + abase_t;
        const uint32_t bstg = sb + (kt % STAGES) * STAGE_BYTES + A_BYTES + bbase_t;

        // preload s = 0 fragments
        {
            const uint32_t ca = (uint32_t)(q_l * 16) ^ mask_a;
            const uint32_t cb = (uint32_t)(q_l * 16) ^ mask_b;
            #pragma unroll
            for (int i = 0; i < 4; ++i) ldsm_x4(a[0][i], astg + i * 2048 + ca);
            #pragma unroll
            for (int t = 0; t < 2; ++t) ldsm_x4(b[0][t], bstg + t * 2048 + cb);
        }

        #pragma unroll
        for (int s = 0; s < 4; ++s) {
            const int cur = s & 1, nxt = cur ^ 1;
            if (s < 3) {       // prefetch s+1 fragments under this step's MMAs
                const uint32_t ca = (uint32_t)((s + 1) * 32 + q_l * 16) ^ mask_a;
                const uint32_t cb = (uint32_t)((s + 1) * 32 + q_l * 16) ^ mask_b;
                #pragma unroll
                for (int i = 0; i < 4; ++i) ldsm_x4(a[nxt][i], astg + i * 2048 + ca);
                #pragma unroll
                for (int t = 0; t < 2; ++t) ldsm_x4(b[nxt][t], bstg + t * 2048 + cb);
            }
            #pragma unroll
            for (int i = 0; i < 4; ++i)
                #pragma unroll
                for (int j = 0; j < 4; ++j)
                    mma_f16(d[i][j], a[cur][i],
                            b[cur][j >> 1][j & 1], b[cur][j >> 1][(j & 1) + 2]);
        }
        // no bottom sync: top-of-next-iter sync orders stage reuse
    }

    // ---- epilogue: + bias, direct float2 stores ----
    const int g  = lane >> 2;
    const int c2 = (lane & 3) * 2;
    #pragma unroll
    for (int j = 0; j < 4; ++j) {
        const int col = n0 + wn + j * 8 + c2;
        const float2 bv = *reinterpret_cast<const float2*>(bias + col);
        #pragma unroll
        for (int i = 0; i < 4; ++i) {
            int r0 = m0 + wm + i * 16 + g;
            if (r0 < M) {
                float2 o = make_float2(d[i][j][0] + bv.x, d[i][j][1] + bv.y);
                *reinterpret_cast<float2*>(out + (size_t)r0 * E + col) = o;
            }
            int r1 = r0 + 8;
            if (r1 < M) {
                float2 o = make_float2(d[i][j][2] + bv.x, d[i][j][3] + bv.y);
                *reinterpret_cast<float2*>(out + (size_t)r1 * E + col) = o;
            }
        }
    }
}

} // namespace

extern "C" void kernel_launch(void* const* d_in, const int* in_sizes, int n_in,
                              void* d_out, int out_size) {
    const float* x     = (const float*)d_in[0];  // [96, 4, 420, 312]
    const float* Wm    = (const float*)d_in[1];  // [768, 672]
    const float* b     = (const float*)d_in[2];  // [768]
    const int*   valid = (const int*)  d_in[3];  // [390]
    float*       out   = (float*)d_out;          // [37440, 768]

    round_wh<<<(NW4 + 255) / 256, 256>>>(Wm);

    cudaFuncSetAttribute(patch_embed_gemm,
                         cudaFuncAttributeMaxDynamicSharedMemorySize, SM_TOTAL);
    patch_embed_gemm<<<NPROD + MBLK * NBLK, 512, SM_TOTAL>>>(x, b, valid, out);
}